// round 15
// baseline (speedup 1.0000x reference)
#include <cuda_runtime.h>
#include <cuda_bf16.h>
#include <math.h>
#include <cstdint>

#define B_  8
#define S_  1024
#define H_  16
#define HD_ 64
#define D_  1024
#define M_  (B_ * S_)       // 8192
// pad additive mask, pre-scaled by log2(e) for the exp2 path
#define PADV_ (-14426.950408889634f)
#define SCL2_ (0.18033688011112042f)   // 0.125 * log2(e)

// ---------------- scratch (no allocs allowed) ----------------
__device__ __nv_bfloat16 g_xb[M_ * D_];
__device__ __nv_bfloat16 g_wqb[D_ * D_];   // native [K][N] layout, bf16
__device__ __nv_bfloat16 g_wkb[D_ * D_];
__device__ __nv_bfloat16 g_wvb[D_ * D_];
__device__ __nv_bfloat16 g_wob[D_ * D_];
__device__ __nv_bfloat16 g_Qb[M_ * D_];    // [B*H][S][HD]
__device__ __nv_bfloat16 g_Kb[M_ * D_];    // compacted keys per (b,h)
__device__ __nv_bfloat16 g_Vb[M_ * D_];    // compacted values per (b,h)
__device__ __nv_bfloat16 g_ctxb[M_ * D_];  // [B*S][D]
__device__ float g_y[M_ * D_];
__device__ int   g_kidx[B_ * S_];          // compacted unmasked key indices
__device__ float g_amask[B_ * S_];         // 0 real key / PADV_ pad (pre-scaled)
__device__ int   g_kcnt[B_];               // unmasked count per batch

// ---------------- helpers ----------------
__device__ __forceinline__ uint32_t smem_u32(const void* p) {
    uint32_t a;
    asm("{ .reg .u64 t; cvta.to.shared.u64 t, %1; cvt.u32.u64 %0, t; }"
        : "=r"(a) : "l"(p));
    return a;
}
__device__ __forceinline__ void cpa16s(uint32_t s, const void* g) {
    asm volatile("cp.async.cg.shared.global [%0], [%1], 16;\n" :: "r"(s), "l"(g));
}
__device__ __forceinline__ void cp_commit() { asm volatile("cp.async.commit_group;\n"); }
__device__ __forceinline__ void cp_wait0()  { asm volatile("cp.async.wait_group 0;\n" ::: "memory"); }
__device__ __forceinline__ void cp_wait1()  { asm volatile("cp.async.wait_group 1;\n" ::: "memory"); }

__device__ __forceinline__ void ldmx4(uint32_t* r, uint32_t addr) {
    asm volatile("ldmatrix.sync.aligned.m8n8.x4.shared.b16 {%0,%1,%2,%3}, [%4];"
        : "=r"(r[0]), "=r"(r[1]), "=r"(r[2]), "=r"(r[3]) : "r"(addr));
}
__device__ __forceinline__ void ldmx4t(uint32_t* r, uint32_t addr) {
    asm volatile("ldmatrix.sync.aligned.m8n8.x4.trans.shared.b16 {%0,%1,%2,%3}, [%4];"
        : "=r"(r[0]), "=r"(r[1]), "=r"(r[2]), "=r"(r[3]) : "r"(addr));
}
__device__ __forceinline__ void mma16816(float* c, const uint32_t* a,
                                         uint32_t b0, uint32_t b1) {
    asm volatile("mma.sync.aligned.m16n8k16.row.col.f32.bf16.bf16.f32 "
        "{%0,%1,%2,%3}, {%4,%5,%6,%7}, {%8,%9}, {%0,%1,%2,%3};"
        : "+f"(c[0]), "+f"(c[1]), "+f"(c[2]), "+f"(c[3])
        : "r"(a[0]), "r"(a[1]), "r"(a[2]), "r"(a[3]), "r"(b0), "r"(b1));
}
__device__ __forceinline__ uint32_t packbf2(float lo, float hi) {
    __nv_bfloat162 t = __floats2bfloat162_rn(lo, hi);
    return *(uint32_t*)&t;
}

// ---------------------------------------------------------------------------
// Fused prologue: fp32->bf16 conversion of x + 4 weights (blocks 0..CVTB-1)
// and per-batch mask scan/compaction (blocks CVTB..CVTB+7).
// ---------------------------------------------------------------------------
#define XN (M_ * D_)          // 8388608
#define WN (D_ * D_)          // 1048576
#define CVTB ((XN + 4 * WN) / 1024)   // 12288

__global__ __launch_bounds__(256) void prologue_kernel(
    const float* __restrict__ x,
    const float* __restrict__ wq, const float* __restrict__ wk,
    const float* __restrict__ wv, const float* __restrict__ wo,
    __nv_bfloat16* __restrict__ xb,
    __nv_bfloat16* __restrict__ wqb, __nv_bfloat16* __restrict__ wkb,
    __nv_bfloat16* __restrict__ wvb, __nv_bfloat16* __restrict__ wob,
    const int* __restrict__ mask, int* __restrict__ kidx,
    float* __restrict__ amask, int* __restrict__ kcnt)
{
    if (blockIdx.x >= CVTB) {
        // ---- mask scan for batch b ----
        __shared__ int m[1024];
        __shared__ int wsum[8];
        __shared__ int totsh;
        const int b = blockIdx.x - CVTB, t = threadIdx.x;
        const int lane = t & 31, w = t >> 5;
#pragma unroll
        for (int i = 0; i < 4; i++) m[t * 4 + i] = mask[b * 1024 + t * 4 + i];
        __syncthreads();
        int f[4], c = 0;
#pragma unroll
        for (int i = 0; i < 4; i++) { f[i] = (m[t * 4 + i] == 0); c += f[i]; }
        int ex = c;
#pragma unroll
        for (int o = 1; o < 32; o <<= 1) {
            int v = __shfl_up_sync(0xffffffffu, ex, o);
            if (lane >= o) ex += v;
        }
        int wtot = __shfl_sync(0xffffffffu, ex, 31);
        ex -= c;
        if (lane == 31) wsum[w] = wtot;
        __syncthreads();
        if (t == 0) {
            int run = 0;
#pragma unroll
            for (int i = 0; i < 8; i++) { int v = wsum[i]; wsum[i] = run; run += v; }
            totsh = run;
            kcnt[b] = run;
        }
        __syncthreads();
        int base = wsum[w] + ex;
        const int total = totsh;
#pragma unroll
        for (int i = 0; i < 4; i++) {
            if (f[i]) kidx[b * 1024 + base++] = t * 4 + i;
        }
#pragma unroll
        for (int i = 0; i < 4; i++) {
            int j = t * 4 + i;
            amask[b * 1024 + j] = (j < total) ? 0.0f : PADV_;
            if (j >= total) kidx[b * 1024 + j] = 0;
        }
        return;
    }

    // ---- fp32 -> bf16 conversion ----
    long long i = (long long)(blockIdx.x * 256 + threadIdx.x) * 4;
    const float* src;
    __nv_bfloat16* dst;
    long long off;
    if (i < XN)                { src = x;  dst = xb;  off = i; }
    else if (i < XN + WN)      { src = wq; dst = wqb; off = i - XN; }
    else if (i < XN + 2 * WN)  { src = wk; dst = wkb; off = i - XN - WN; }
    else if (i < XN + 3 * WN)  { src = wv; dst = wvb; off = i - XN - 2 * WN; }
    else                       { src = wo; dst = wob; off = i - XN - 3 * WN; }
    float4 v = *(const float4*)(src + off);
    *(__nv_bfloat162*)(dst + off)     = __floats2bfloat162_rn(v.x, v.y);
    *(__nv_bfloat162*)(dst + off + 2) = __floats2bfloat162_rn(v.z, v.w);
}

// ---------------------------------------------------------------------------
// mma.sync GEMM: block 128x128, 8 warps 2(m)x4(n), warp 64x32, BK=64,
// 3-stage ring, one sync per K-step. Per-thread load pointers/offsets are
// hoisted out of the pipeline loop (compiler can't hoist across barriers).
// gather mode (heads_mode && z!=0): A-rows gathered through kidx; pad-region
// CTAs exit immediately.
// ---------------------------------------------------------------------------
#define GAST 18432
#define GBST 17408
#define GBBASE (3 * GAST)
#define GSIDX (3 * GAST + 3 * GBST)       // row-index array (128 ints)
#define GEMM_SMEM (GSIDX + 512)

__global__ __launch_bounds__(256, 2) void gemm_mma_kernel(
    const __nv_bfloat16* __restrict__ A,
    const __nv_bfloat16* __restrict__ W0, const __nv_bfloat16* __restrict__ W1,
    const __nv_bfloat16* __restrict__ W2,
    const float* __restrict__ b0p, const float* __restrict__ b1p,
    const float* __restrict__ b2p,
    const float* __restrict__ resid,
    __nv_bfloat16* __restrict__ O0, __nv_bfloat16* __restrict__ O1,
    __nv_bfloat16* __restrict__ O2,
    float* __restrict__ OutF, int heads_mode,
    const int* __restrict__ kidx, const int* __restrict__ kcnt)
{
    extern __shared__ char smraw[];
    const uint32_t sb = smem_u32(smraw);
    const int tid = threadIdx.x;
    const int wid = tid >> 5, lane = tid & 31;
    const int wm = wid >> 2, wn = wid & 3;
    const int bm = blockIdx.y * 128, bn = blockIdx.x * 128;
    const int z = blockIdx.z;

    const int gather = heads_mode && (z != 0);
    if (gather) {
        const int cnt = kcnt[bm >> 10];
        if ((bm & 1023) >= ((cnt + 127) & ~127)) return;
    }

    const __nv_bfloat16* W = (z == 0) ? W0 : (z == 1) ? W1 : W2;
    const float* bias       = (z == 0) ? b0p : (z == 1) ? b1p : b2p;
    __nv_bfloat16* OutB     = (z == 0) ? O0 : (z == 1) ? O1 : O2;

    int* srows = (int*)(smraw + GSIDX);
    if (tid < 128) {
        int m = bm + tid;
        srows[tid] = gather ? ((m & ~1023) + kidx[m]) : m;
    }
    __syncthreads();

    const __nv_bfloat16* Wg = W + bn;

    // hoisted per-thread load pointers + smem offsets (loop-invariant)
    const __nv_bfloat16* arow[4];
    const __nv_bfloat16* wrow[4];
    uint32_t aoff[4], boff[4];
#pragma unroll
    for (int i = 0; i < 4; i++) {
        int idx = i * 256 + tid;
        int ra = idx >> 3, ca = (idx & 7) * 8;
        arow[i] = A + (size_t)srows[ra] * D_ + ca;
        aoff[i] = (uint32_t)(ra * 72 + ca) * 2;
        int rb = idx >> 4, cb = (idx & 15) * 8;
        wrow[i] = Wg + (size_t)rb * D_ + cb;
        boff[i] = (uint32_t)(rb * 136 + cb) * 2;
    }

    float acc[16][4];
#pragma unroll
    for (int i = 0; i < 16; i++)
#pragma unroll
        for (int j = 0; j < 4; j++) acc[i][j] = 0.f;

#define GLOAD(u, st) do { \
        const uint32_t as = sb + (st) * GAST; \
        const uint32_t bs = sb + GBBASE + (st) * GBST; \
        _Pragma("unroll") \
        for (int i = 0; i < 4; i++) { \
            cpa16s(as + aoff[i], arow[i] + (u) * 64); \
            cpa16s(bs + boff[i], wrow[i] + (size_t)((u) * 64) * D_); \
        } \
    } while (0)

    GLOAD(0, 0); cp_commit();
    GLOAD(1, 1); cp_commit();

    int sr = 0, sw = 2;
    for (int u = 0; u < 16; u++) {
        cp_wait1();
        __syncthreads();
        if (u + 2 < 16) GLOAD(u + 2, sw);
        cp_commit();

        const uint32_t as = sb + sr * GAST;
        const uint32_t bs = sb + GBBASE + sr * GBST;
#pragma unroll
        for (int kk = 0; kk < 4; kk++) {
            uint32_t a[4][4];
#pragma unroll
            for (int i = 0; i < 4; i++) {
                int row = wm * 64 + i * 16 + (lane & 7) + ((lane >> 3) & 1) * 8;
                int col = kk * 16 + (lane >> 4) * 8;
                ldmx4(a[i], as + (uint32_t)(row * 72 + col) * 2);
            }
#pragma unroll
            for (int jp = 0; jp < 2; jp++) {
                int row = kk * 16 + (lane & 7) + ((lane >> 3) & 1) * 8;
                int col = wn * 32 + jp * 16 + (lane >> 4) * 8;
                uint32_t r4[4];
                ldmx4t(r4, bs + (uint32_t)(row * 136 + col) * 2);
#pragma unroll
                for (int i = 0; i < 4; i++) {
                    mma16816(acc[i * 4 + jp * 2],     a[i], r4[0], r4[1]);
                    mma16816(acc[i * 4 + jp * 2 + 1], a[i], r4[2], r4[3]);
                }
            }
        }
        sr = (sr == 2) ? 0 : sr + 1;
        sw = (sw == 2) ? 0 : sw + 1;
    }
#undef GLOAD

#pragma unroll
    for (int i = 0; i < 4; i++) {
        const int m0 = bm + wm * 64 + i * 16 + (lane >> 2);
#pragma unroll
        for (int j = 0; j < 4; j++) {
            const int n = bn + wn * 32 + j * 8 + 2 * (lane & 3);
            const float2 bb = *(const float2*)(bias + n);
            float v0 = acc[i * 4 + j][0] + bb.x;
            float v1 = acc[i * 4 + j][1] + bb.y;
            float v2 = acc[i * 4 + j][2] + bb.x;
            float v3 = acc[i * 4 + j][3] + bb.y;
            if (heads_mode) {
                const int h = n >> 6, hd = n & 63;
                {
                    int b = m0 >> 10, s = m0 & 1023;
                    *(__nv_bfloat162*)(OutB + (((size_t)((b << 4) + h)) << 16)
                                       + ((size_t)s << 6) + hd)
                        = __floats2bfloat162_rn(v0, v1);
                }
                {
                    int m1 = m0 + 8;
                    int b = m1 >> 10, s = m1 & 1023;
                    *(__nv_bfloat162*)(OutB + (((size_t)((b << 4) + h)) << 16)
                                       + ((size_t)s << 6) + hd)
                        = __floats2bfloat162_rn(v2, v3);
                }
            } else {
                size_t off0 = (size_t)m0 * D_ + n;
                size_t off1 = (size_t)(m0 + 8) * D_ + n;
                float2 r0 = *(const float2*)(resid + off0);
                float2 r1 = *(const float2*)(resid + off1);
                *(float2*)(OutF + off0) = make_float2(v0 + r0.x, v1 + r0.y);
                *(float2*)(OutF + off1) = make_float2(v2 + r1.x, v3 + r1.y);
            }
        }
    }
}

// ---------------------------------------------------------------------------
// Attention over PRE-COMPACTED K/V: direct sequential loads, 4 warps x 32
// q-rows, 64-key half-tiles. exp via exp2 with pre-merged constants.
// Per-thread load pointers hoisted out of the tile loop.
// ---------------------------------------------------------------------------
#define AQOFF 0
#define AKOFF 18432
#define AVOFF (18432 + 18432)
#define AMOFF (18432 + 36864)
#define ATTN_SMEM (18432 + 36864 + 512 + 128)

__global__ __launch_bounds__(128, 2) void attn_kernel(
    const __nv_bfloat16* __restrict__ Q, const __nv_bfloat16* __restrict__ K,
    const __nv_bfloat16* __restrict__ V,
    const float* __restrict__ amask, const int* __restrict__ kcnt,
    __nv_bfloat16* __restrict__ ctx)
{
    extern __shared__ char smraw[];
    const uint32_t sb = smem_u32(smraw);
    const int tid = threadIdx.x;
    const int wid = tid >> 5, lane = tid & 31;
    const int bh = blockIdx.y;
    const int b = bh >> 4, h = bh & 15;
    const int q0 = blockIdx.x * 128;

    const __nv_bfloat16* Qp = Q + (((size_t)bh) << 16) + (size_t)q0 * HD_;
    const __nv_bfloat16* Kp = K + (((size_t)bh) << 16);
    const __nv_bfloat16* Vp = V + (((size_t)bh) << 16);
    const float* amp = amask + b * 1024;
    const int nh = (kcnt[b] + 63) >> 6;

#pragma unroll
    for (int i = 0; i < 8; i++) {
        int l = i * 128 + tid;
        int r = l >> 3, c = (l & 7) * 8;
        cpa16s(sb + AQOFF + (uint32_t)(r * 72 + c) * 2, Qp + (size_t)r * HD_ + c);
    }

    // hoisted per-thread K/V load pointers + smem offsets
    const __nv_bfloat16* krow[4];
    const __nv_bfloat16* vrow[4];
    uint32_t kvoff[4];
#pragma unroll
    for (int ii = 0; ii < 4; ii++) {
        int l = ii * 128 + tid;
        int r = l >> 3, c = (l & 7) * 8;
        krow[ii] = Kp + (size_t)r * HD_ + c;
        vrow[ii] = Vp + (size_t)r * HD_ + c;
        kvoff[ii] = (uint32_t)(r * 72 + c) * 2;
    }

#define LOADH(ih, buf) do { \
        const int koff = (ih) * 64 * HD_; \
        _Pragma("unroll") \
        for (int ii = 0; ii < 4; ii++) { \
            cpa16s(sb + AKOFF + (buf) * 9216 + kvoff[ii], krow[ii] + koff); \
            cpa16s(sb + AVOFF + (buf) * 9216 + kvoff[ii], vrow[ii] + koff); \
        } \
        if (tid < 16) cpa16s(sb + AMOFF + (buf) * 256 + tid * 16, \
                             amp + (ih) * 64 + tid * 4); \
    } while (0)

    LOADH(0, 0);
    cp_commit();

    uint32_t qf[2][4][4];
    float oacc[2][8][4];
#pragma unroll
    for (int mi = 0; mi < 2; mi++)
#pragma unroll
        for (int i = 0; i < 8; i++)
#pragma unroll
            for (int j = 0; j < 4; j++) oacc[mi][i][j] = 0.f;
    float lsum[2][2] = {{0.f, 0.f}, {0.f, 0.f}};

    for (int ih = 0; ih < nh; ih++) {
        cp_wait0();
        __syncthreads();
        if (ih + 1 < nh) LOADH(ih + 1, (ih + 1) & 1);
        cp_commit();

        if (ih == 0) {
#pragma unroll
            for (int mi = 0; mi < 2; mi++)
#pragma unroll
                for (int kk = 0; kk < 4; kk++) {
                    int row = wid * 32 + mi * 16 + (lane & 7) + ((lane >> 3) & 1) * 8;
                    int col = kk * 16 + (lane >> 4) * 8;
                    ldmx4(qf[mi][kk], sb + AQOFF + (uint32_t)(row * 72 + col) * 2);
                }
        }

        const int buf = ih & 1;
        const uint32_t ksb = sb + AKOFF + buf * 9216;
        const uint32_t vsb = sb + AVOFF + buf * 9216;
        const float* mskf = (const float*)(smraw + AMOFF + buf * 256);

        float sacc[2][8][4];
#pragma unroll
        for (int mi = 0; mi < 2; mi++)
#pragma unroll
            for (int i = 0; i < 8; i++)
#pragma unroll
                for (int j = 0; j < 4; j++) sacc[mi][i][j] = 0.f;

#pragma unroll
        for (int kk = 0; kk < 4; kk++) {
#pragma unroll
            for (int jp = 0; jp < 4; jp++) {
                int row = jp * 16 + (lane & 7) + ((lane >> 3) & 1) * 8;
                int col = kk * 16 + (lane >> 4) * 8;
                uint32_t r4[4];
                ldmx4(r4, ksb + (uint32_t)(row * 72 + col) * 2);
#pragma unroll
                for (int mi = 0; mi < 2; mi++) {
                    mma16816(sacc[mi][jp * 2],     qf[mi][kk], r4[0], r4[2]);
                    mma16816(sacc[mi][jp * 2 + 1], qf[mi][kk], r4[1], r4[3]);
                }
            }
        }

        uint32_t pf[2][4][4];
#pragma unroll
        for (int mi = 0; mi < 2; mi++) {
#pragma unroll
            for (int j = 0; j < 8; j++) {
                const int n0 = j * 8 + 2 * (lane & 3);
                const float mk0 = mskf[n0];
                const float mk1 = mskf[n0 + 1];
                float e0 = exp2f(fmaf(sacc[mi][j][0], SCL2_, mk0));
                float e1 = exp2f(fmaf(sacc[mi][j][1], SCL2_, mk1));
                float e2 = exp2f(fmaf(sacc[mi][j][2], SCL2_, mk0));
                float e3 = exp2f(fmaf(sacc[mi][j][3], SCL2_, mk1));
                lsum[mi][0] += e0 + e1;
                lsum[mi][1] += e2 + e3;
                const int kk2 = j >> 1;
                if ((j & 1) == 0) {
                    pf[mi][kk2][0] = packbf2(e0, e1);
                    pf[mi][kk2][1] = packbf2(e2, e3);
                } else {
                    pf[mi][kk2][2] = packbf2(e0, e1);
                    pf[mi][kk2][3] = packbf2(e2, e3);
                }
            }
        }

#pragma unroll
        for (int kk2 = 0; kk2 < 4; kk2++) {
#pragma unroll
            for (int jp = 0; jp < 4; jp++) {
                int row = kk2 * 16 + (lane & 7) + ((lane >> 3) & 1) * 8;
                int col = jp * 16 + (lane >> 4) * 8;
                uint32_t r4[4];
                ldmx4t(r4, vsb + (uint32_t)(row * 72 + col) * 2);
#pragma unroll
                for (int mi = 0; mi < 2; mi++) {
                    mma16816(oacc[mi][jp * 2],     pf[mi][kk2], r4[0], r4[1]);
                    mma16816(oacc[mi][jp * 2 + 1], pf[mi][kk2], r4[2], r4[3]);
                }
            }
        }
    }
#undef LOADH

#pragma unroll
    for (int mi = 0; mi < 2; mi++) {
        lsum[mi][0] += __shfl_xor_sync(0xffffffffu, lsum[mi][0], 1);
        lsum[mi][0] += __shfl_xor_sync(0xffffffffu, lsum[mi][0], 2);
        lsum[mi][1] += __shfl_xor_sync(0xffffffffu, lsum[mi][1], 1);
        lsum[mi][1] += __shfl_xor_sync(0xffffffffu, lsum[mi][1], 2);
        const float inv0 = 1.0f / lsum[mi][0];
        const float inv1 = 1.0f / lsum[mi][1];
        const int row0 = q0 + wid * 32 + mi * 16 + (lane >> 2);
#pragma unroll
        for (int j2 = 0; j2 < 8; j2++) {
            const int col = h * HD_ + j2 * 8 + 2 * (lane & 3);
            size_t off0 = (size_t)(b * S_ + row0) * D_ + col;
            size_t off1 = (size_t)(b * S_ + row0 + 8) * D_ + col;
            *(__nv_bfloat162*)(ctx + off0) =
                __floats2bfloat162_rn(oacc[mi][j2][0] * inv0, oacc[mi][j2][1] * inv0);
            *(__nv_bfloat162*)(ctx + off1) =
                __floats2bfloat162_rn(oacc[mi][j2][2] * inv1, oacc[mi][j2][3] * inv1);
        }
    }
}

// ---------------------------------------------------------------------------
// Row LayerNorm over [M, 1024]: warp-per-row, barrier-free.
// ---------------------------------------------------------------------------
__global__ __launch_bounds__(256) void ln_kernel(
    const float* __restrict__ Y, const float* __restrict__ gamma,
    const float* __restrict__ beta, float* __restrict__ O)
{
    const int wid = threadIdx.x >> 5, lane = threadIdx.x & 31;
    const int row = blockIdx.x * 8 + wid;
    const float* yr = Y + (size_t)row * D_;
    float4 v[8];
    float s = 0.f, sq = 0.f;
#pragma unroll
    for (int i = 0; i < 8; i++) {
        v[i] = *(const float4*)(yr + i * 128 + lane * 4);
        s  += v[i].x + v[i].y + v[i].z + v[i].w;
        sq += v[i].x * v[i].x + v[i].y * v[i].y
            + v[i].z * v[i].z + v[i].w * v[i].w;
    }
#pragma unroll
    for (int o = 16; o; o >>= 1) {
        s  += __shfl_xor_sync(0xffffffffu, s, o);
        sq += __shfl_xor_sync(0xffffffffu, sq, o);
    }
    const float mu   = s * (1.0f / D_);
    const float var  = sq * (1.0f / D_) - mu * mu;
    const float rstd = rsqrtf(var + 1e-6f);
    float* orow = O + (size_t)row * D_;
#pragma unroll
    for (int i = 0; i < 8; i++) {
        const float4 g  = *(const float4*)(gamma + i * 128 + lane * 4);
        const float4 be = *(const float4*)(beta  + i * 128 + lane * 4);
        float4 o;
        o.x = (v[i].x - mu) * rstd * g.x + be.x;
        o.y = (v[i].y - mu) * rstd * g.y + be.y;
        o.z = (v[i].z - mu) * rstd * g.z + be.z;
        o.w = (v[i].w - mu) * rstd * g.w + be.w;
        *(float4*)(orow + i * 128 + lane * 4) = o;
    }
}

// ---------------------------------------------------------------------------
// Launch
// ---------------------------------------------------------------------------
extern "C" void kernel_launch(void* const* d_in, const int* in_sizes, int n_in,
                              void* d_out, int out_size)
{
    const float* x     = (const float*)d_in[0];
    const int*   mask  = (const int*)d_in[1];
    const float* wq    = (const float*)d_in[2];
    const float* bq    = (const float*)d_in[3];
    const float* wk    = (const float*)d_in[4];
    const float* bk    = (const float*)d_in[5];
    const float* wv    = (const float*)d_in[6];
    const float* bv    = (const float*)d_in[7];
    const float* wo    = (const float*)d_in[8];
    const float* bo    = (const float*)d_in[9];
    const float* gamma = (const float*)d_in[10];
    const float* beta  = (const float*)d_in[11];
    float* out = (float*)d_out;

    __nv_bfloat16 *xb, *wqb, *wkb, *wvb, *wob, *Qb, *Kb, *Vb, *ctxb;
    float *yp, *amaskp;
    int *kidxp, *kcntp;
    cudaGetSymbolAddress((void**)&xb,  g_xb);
    cudaGetSymbolAddress((void**)&wqb, g_wqb);
    cudaGetSymbolAddress((void**)&wkb, g_wkb);
    cudaGetSymbolAddress((void**)&wvb, g_wvb);
    cudaGetSymbolAddress((void**)&wob, g_wob);
    cudaGetSymbolAddress((void**)&Qb,  g_Qb);
    cudaGetSymbolAddress((void**)&Kb,  g_Kb);
    cudaGetSymbolAddress((void**)&Vb,  g_Vb);
    cudaGetSymbolAddress((void**)&ctxb, g_ctxb);
    cudaGetSymbolAddress((void**)&yp,  g_y);
    cudaGetSymbolAddress((void**)&kidxp,  g_kidx);
    cudaGetSymbolAddress((void**)&amaskp, g_amask);
    cudaGetSymbolAddress((void**)&kcntp,  g_kcnt);

    cudaFuncSetAttribute(gemm_mma_kernel,
                         cudaFuncAttributeMaxDynamicSharedMemorySize, GEMM_SMEM);
    cudaFuncSetAttribute(attn_kernel,
                         cudaFuncAttributeMaxDynamicSharedMemorySize, ATTN_SMEM);

    prologue_kernel<<<CVTB + B_, 256>>>(
        x, wq, wk, wv, wo, xb, wqb, wkb, wvb, wob,
        mask, kidxp, amaskp, kcntp);

    dim3 gQKV(D_ / 128, M_ / 128, 3);   // (8, 64, 3); K/V CTAs self-prune
    gemm_mma_kernel<<<gQKV, 256, GEMM_SMEM>>>(
        xb, wqb, wkb, wvb, bq, bk, bv, nullptr, Qb, Kb, Vb, nullptr, 1,
        kidxp, kcntp);

    dim3 gAttn(S_ / 128, B_ * H_);      // (8, 128)
    attn_kernel<<<gAttn, 128, ATTN_SMEM>>>(Qb, Kb, Vb, amaskp, kcntp, ctxb);

    dim3 gO(D_ / 128, M_ / 128, 1);
    gemm_mma_kernel<<<gO, 256, GEMM_SMEM>>>(
        ctxb, wob, wob, wob, bo, bo, bo, x, nullptr, nullptr, nullptr, yp, 0,
        kidxp, kcntp);

    ln_kernel<<<M_ / 8, 256>>>(yp, gamma, beta, out);
}

// round 16
// speedup vs baseline: 1.0172x; 1.0172x over previous
#include <cuda_runtime.h>
#include <cuda_bf16.h>
#include <math.h>
#include <cstdint>

#define B_  8
#define S_  1024
#define H_  16
#define HD_ 64
#define D_  1024
#define M_  (B_ * S_)       // 8192
// pad additive mask, pre-scaled by log2(e) for the exp2 path
#define PADV_ (-14426.950408889634f)
#define SCL2_ (0.18033688011112042f)   // 0.125 * log2(e)

// ---------------- scratch (no allocs allowed) ----------------
__device__ __nv_bfloat16 g_xb[M_ * D_];
__device__ __nv_bfloat16 g_wqb[D_ * D_];   // native [K][N] layout, bf16
__device__ __nv_bfloat16 g_wkb[D_ * D_];
__device__ __nv_bfloat16 g_wvb[D_ * D_];
__device__ __nv_bfloat16 g_wob[D_ * D_];
__device__ __nv_bfloat16 g_Qb[M_ * D_];    // [B*H][S][HD]
__device__ __nv_bfloat16 g_Kb[M_ * D_];    // compacted keys per (b,h)
__device__ __nv_bfloat16 g_Vb[M_ * D_];    // compacted values per (b,h)
__device__ __nv_bfloat16 g_ctxb[M_ * D_];  // [B*S][D]
__device__ float g_y[M_ * D_];
__device__ int   g_kidx[B_ * S_];          // compacted unmasked key indices
__device__ float g_amask[B_ * S_];         // 0 real key / PADV_ pad (pre-scaled)
__device__ int   g_kcnt[B_];               // unmasked count per batch

// ---------------- helpers ----------------
__device__ __forceinline__ uint32_t smem_u32(const void* p) {
    uint32_t a;
    asm("{ .reg .u64 t; cvta.to.shared.u64 t, %1; cvt.u32.u64 %0, t; }"
        : "=r"(a) : "l"(p));
    return a;
}
__device__ __forceinline__ void cpa16s(uint32_t s, const void* g) {
    asm volatile("cp.async.cg.shared.global [%0], [%1], 16;\n" :: "r"(s), "l"(g));
}
__device__ __forceinline__ void cp_commit() { asm volatile("cp.async.commit_group;\n"); }
__device__ __forceinline__ void cp_wait0()  { asm volatile("cp.async.wait_group 0;\n" ::: "memory"); }
__device__ __forceinline__ void cp_wait1()  { asm volatile("cp.async.wait_group 1;\n" ::: "memory"); }

__device__ __forceinline__ void ldmx4(uint32_t* r, uint32_t addr) {
    asm volatile("ldmatrix.sync.aligned.m8n8.x4.shared.b16 {%0,%1,%2,%3}, [%4];"
        : "=r"(r[0]), "=r"(r[1]), "=r"(r[2]), "=r"(r[3]) : "r"(addr));
}
__device__ __forceinline__ void ldmx4t(uint32_t* r, uint32_t addr) {
    asm volatile("ldmatrix.sync.aligned.m8n8.x4.trans.shared.b16 {%0,%1,%2,%3}, [%4];"
        : "=r"(r[0]), "=r"(r[1]), "=r"(r[2]), "=r"(r[3]) : "r"(addr));
}
__device__ __forceinline__ void mma16816(float* c, const uint32_t* a,
                                         uint32_t b0, uint32_t b1) {
    asm volatile("mma.sync.aligned.m16n8k16.row.col.f32.bf16.bf16.f32 "
        "{%0,%1,%2,%3}, {%4,%5,%6,%7}, {%8,%9}, {%0,%1,%2,%3};"
        : "+f"(c[0]), "+f"(c[1]), "+f"(c[2]), "+f"(c[3])
        : "r"(a[0]), "r"(a[1]), "r"(a[2]), "r"(a[3]), "r"(b0), "r"(b1));
}
__device__ __forceinline__ uint32_t packbf2(float lo, float hi) {
    __nv_bfloat162 t = __floats2bfloat162_rn(lo, hi);
    return *(uint32_t*)&t;
}

// ---------------------------------------------------------------------------
// Fused prologue: fp32->bf16 conversion of x + 4 weights (blocks 0..CVTB-1)
// and per-batch mask scan/compaction (blocks CVTB..CVTB+7).
// ---------------------------------------------------------------------------
#define XN (M_ * D_)          // 8388608
#define WN (D_ * D_)          // 1048576
#define CVTB ((XN + 4 * WN) / 1024)   // 12288

__global__ __launch_bounds__(256) void prologue_kernel(
    const float* __restrict__ x,
    const float* __restrict__ wq, const float* __restrict__ wk,
    const float* __restrict__ wv, const float* __restrict__ wo,
    __nv_bfloat16* __restrict__ xb,
    __nv_bfloat16* __restrict__ wqb, __nv_bfloat16* __restrict__ wkb,
    __nv_bfloat16* __restrict__ wvb, __nv_bfloat16* __restrict__ wob,
    const int* __restrict__ mask, int* __restrict__ kidx,
    float* __restrict__ amask, int* __restrict__ kcnt)
{
    if (blockIdx.x >= CVTB) {
        // ---- mask scan for batch b ----
        __shared__ int m[1024];
        __shared__ int wsum[8];
        __shared__ int totsh;
        const int b = blockIdx.x - CVTB, t = threadIdx.x;
        const int lane = t & 31, w = t >> 5;
#pragma unroll
        for (int i = 0; i < 4; i++) m[t * 4 + i] = mask[b * 1024 + t * 4 + i];
        __syncthreads();
        int f[4], c = 0;
#pragma unroll
        for (int i = 0; i < 4; i++) { f[i] = (m[t * 4 + i] == 0); c += f[i]; }
        int ex = c;
#pragma unroll
        for (int o = 1; o < 32; o <<= 1) {
            int v = __shfl_up_sync(0xffffffffu, ex, o);
            if (lane >= o) ex += v;
        }
        int wtot = __shfl_sync(0xffffffffu, ex, 31);
        ex -= c;
        if (lane == 31) wsum[w] = wtot;
        __syncthreads();
        if (t == 0) {
            int run = 0;
#pragma unroll
            for (int i = 0; i < 8; i++) { int v = wsum[i]; wsum[i] = run; run += v; }
            totsh = run;
            kcnt[b] = run;
        }
        __syncthreads();
        int base = wsum[w] + ex;
        const int total = totsh;
#pragma unroll
        for (int i = 0; i < 4; i++) {
            if (f[i]) kidx[b * 1024 + base++] = t * 4 + i;
        }
#pragma unroll
        for (int i = 0; i < 4; i++) {
            int j = t * 4 + i;
            amask[b * 1024 + j] = (j < total) ? 0.0f : PADV_;
            if (j >= total) kidx[b * 1024 + j] = 0;
        }
        return;
    }

    // ---- fp32 -> bf16 conversion ----
    long long i = (long long)(blockIdx.x * 256 + threadIdx.x) * 4;
    const float* src;
    __nv_bfloat16* dst;
    long long off;
    if (i < XN)                { src = x;  dst = xb;  off = i; }
    else if (i < XN + WN)      { src = wq; dst = wqb; off = i - XN; }
    else if (i < XN + 2 * WN)  { src = wk; dst = wkb; off = i - XN - WN; }
    else if (i < XN + 3 * WN)  { src = wv; dst = wvb; off = i - XN - 2 * WN; }
    else                       { src = wo; dst = wob; off = i - XN - 3 * WN; }
    float4 v = *(const float4*)(src + off);
    *(__nv_bfloat162*)(dst + off)     = __floats2bfloat162_rn(v.x, v.y);
    *(__nv_bfloat162*)(dst + off + 2) = __floats2bfloat162_rn(v.z, v.w);
}

// ---------------------------------------------------------------------------
// mma.sync GEMM: block 128x128, 8 warps 2(m)x4(n), warp 64x32, BK=64,
// 3-stage ring, one sync per K-step.
// gather mode (heads_mode && z!=0): A-rows gathered through kidx; pad-region
// CTAs exit immediately.
// ---------------------------------------------------------------------------
#define GAST 18432
#define GBST 17408
#define GBBASE (3 * GAST)
#define GSIDX (3 * GAST + 3 * GBST)       // row-index array (128 ints)
#define GEMM_SMEM (GSIDX + 512)

__global__ __launch_bounds__(256, 2) void gemm_mma_kernel(
    const __nv_bfloat16* __restrict__ A,
    const __nv_bfloat16* __restrict__ W0, const __nv_bfloat16* __restrict__ W1,
    const __nv_bfloat16* __restrict__ W2,
    const float* __restrict__ b0p, const float* __restrict__ b1p,
    const float* __restrict__ b2p,
    const float* __restrict__ resid,
    __nv_bfloat16* __restrict__ O0, __nv_bfloat16* __restrict__ O1,
    __nv_bfloat16* __restrict__ O2,
    float* __restrict__ OutF, int heads_mode,
    const int* __restrict__ kidx, const int* __restrict__ kcnt)
{
    extern __shared__ char smraw[];
    const uint32_t sb = smem_u32(smraw);
    const int tid = threadIdx.x;
    const int wid = tid >> 5, lane = tid & 31;
    const int wm = wid >> 2, wn = wid & 3;
    const int bm = blockIdx.y * 128, bn = blockIdx.x * 128;
    const int z = blockIdx.z;

    const int gather = heads_mode && (z != 0);
    if (gather) {
        const int cnt = kcnt[bm >> 10];
        if ((bm & 1023) >= ((cnt + 127) & ~127)) return;
    }

    const __nv_bfloat16* W = (z == 0) ? W0 : (z == 1) ? W1 : W2;
    const float* bias       = (z == 0) ? b0p : (z == 1) ? b1p : b2p;
    __nv_bfloat16* OutB     = (z == 0) ? O0 : (z == 1) ? O1 : O2;

    int* srows = (int*)(smraw + GSIDX);
    if (tid < 128) {
        int m = bm + tid;
        srows[tid] = gather ? ((m & ~1023) + kidx[m]) : m;
    }
    __syncthreads();

    const __nv_bfloat16* Wg = W + bn;

    float acc[16][4];
#pragma unroll
    for (int i = 0; i < 16; i++)
#pragma unroll
        for (int j = 0; j < 4; j++) acc[i][j] = 0.f;

#define GLOAD(u, st) do { \
        const uint32_t as = sb + (st) * GAST; \
        const uint32_t bs = sb + GBBASE + (st) * GBST; \
        const __nv_bfloat16* wp = Wg + (size_t)((u) * 64) * D_; \
        _Pragma("unroll") \
        for (int i = 0; i < 4; i++) { \
            int idx = i * 256 + tid; \
            int ra = idx >> 3, ca = (idx & 7) * 8; \
            cpa16s(as + (uint32_t)(ra * 72 + ca) * 2, \
                   A + (size_t)srows[ra] * D_ + (u) * 64 + ca); \
            int rb = idx >> 4, cb = (idx & 15) * 8; \
            cpa16s(bs + (uint32_t)(rb * 136 + cb) * 2, wp + (size_t)rb * D_ + cb); \
        } \
    } while (0)

    GLOAD(0, 0); cp_commit();
    GLOAD(1, 1); cp_commit();

    int sr = 0, sw = 2;
    for (int u = 0; u < 16; u++) {
        cp_wait1();
        __syncthreads();
        if (u + 2 < 16) GLOAD(u + 2, sw);
        cp_commit();

        const uint32_t as = sb + sr * GAST;
        const uint32_t bs = sb + GBBASE + sr * GBST;
#pragma unroll
        for (int kk = 0; kk < 4; kk++) {
            uint32_t a[4][4];
#pragma unroll
            for (int i = 0; i < 4; i++) {
                int row = wm * 64 + i * 16 + (lane & 7) + ((lane >> 3) & 1) * 8;
                int col = kk * 16 + (lane >> 4) * 8;
                ldmx4(a[i], as + (uint32_t)(row * 72 + col) * 2);
            }
#pragma unroll
            for (int jp = 0; jp < 2; jp++) {
                int row = kk * 16 + (lane & 7) + ((lane >> 3) & 1) * 8;
                int col = wn * 32 + jp * 16 + (lane >> 4) * 8;
                uint32_t r4[4];
                ldmx4t(r4, bs + (uint32_t)(row * 136 + col) * 2);
#pragma unroll
                for (int i = 0; i < 4; i++) {
                    mma16816(acc[i * 4 + jp * 2],     a[i], r4[0], r4[1]);
                    mma16816(acc[i * 4 + jp * 2 + 1], a[i], r4[2], r4[3]);
                }
            }
        }
        sr = (sr == 2) ? 0 : sr + 1;
        sw = (sw == 2) ? 0 : sw + 1;
    }
#undef GLOAD

#pragma unroll
    for (int i = 0; i < 4; i++) {
        const int m0 = bm + wm * 64 + i * 16 + (lane >> 2);
#pragma unroll
        for (int j = 0; j < 4; j++) {
            const int n = bn + wn * 32 + j * 8 + 2 * (lane & 3);
            const float2 bb = *(const float2*)(bias + n);
            float v0 = acc[i * 4 + j][0] + bb.x;
            float v1 = acc[i * 4 + j][1] + bb.y;
            float v2 = acc[i * 4 + j][2] + bb.x;
            float v3 = acc[i * 4 + j][3] + bb.y;
            if (heads_mode) {
                const int h = n >> 6, hd = n & 63;
                {
                    int b = m0 >> 10, s = m0 & 1023;
                    *(__nv_bfloat162*)(OutB + (((size_t)((b << 4) + h)) << 16)
                                       + ((size_t)s << 6) + hd)
                        = __floats2bfloat162_rn(v0, v1);
                }
                {
                    int m1 = m0 + 8;
                    int b = m1 >> 10, s = m1 & 1023;
                    *(__nv_bfloat162*)(OutB + (((size_t)((b << 4) + h)) << 16)
                                       + ((size_t)s << 6) + hd)
                        = __floats2bfloat162_rn(v2, v3);
                }
            } else {
                size_t off0 = (size_t)m0 * D_ + n;
                size_t off1 = (size_t)(m0 + 8) * D_ + n;
                float2 r0 = *(const float2*)(resid + off0);
                float2 r1 = *(const float2*)(resid + off1);
                *(float2*)(OutF + off0) = make_float2(v0 + r0.x, v1 + r0.y);
                *(float2*)(OutF + off1) = make_float2(v2 + r1.x, v3 + r1.y);
            }
        }
    }
}

// ---------------------------------------------------------------------------
// Attention over PRE-COMPACTED K/V: direct sequential loads, 4 warps x 32
// q-rows, 64-key half-tiles. exp via exp2 with pre-merged constants.
// ---------------------------------------------------------------------------
#define AQOFF 0
#define AKOFF 18432
#define AVOFF (18432 + 18432)
#define AMOFF (18432 + 36864)
#define ATTN_SMEM (18432 + 36864 + 512 + 128)

__global__ __launch_bounds__(128, 2) void attn_kernel(
    const __nv_bfloat16* __restrict__ Q, const __nv_bfloat16* __restrict__ K,
    const __nv_bfloat16* __restrict__ V,
    const float* __restrict__ amask, const int* __restrict__ kcnt,
    __nv_bfloat16* __restrict__ ctx)
{
    extern __shared__ char smraw[];
    const uint32_t sb = smem_u32(smraw);
    const int tid = threadIdx.x;
    const int wid = tid >> 5, lane = tid & 31;
    const int bh = blockIdx.y;
    const int b = bh >> 4, h = bh & 15;
    const int q0 = blockIdx.x * 128;

    const __nv_bfloat16* Qp = Q + (((size_t)bh) << 16) + (size_t)q0 * HD_;
    const __nv_bfloat16* Kp = K + (((size_t)bh) << 16);
    const __nv_bfloat16* Vp = V + (((size_t)bh) << 16);
    const float* amp = amask + b * 1024;
    const int nh = (kcnt[b] + 63) >> 6;

#pragma unroll
    for (int i = 0; i < 8; i++) {
        int l = i * 128 + tid;
        int r = l >> 3, c = (l & 7) * 8;
        cpa16s(sb + AQOFF + (uint32_t)(r * 72 + c) * 2, Qp + (size_t)r * HD_ + c);
    }
#define LOADH(ih, buf) do { \
        const int k0 = (ih) * 64; \
        _Pragma("unroll") \
        for (int ii = 0; ii < 4; ii++) { \
            int l = ii * 128 + tid; int r = l >> 3, c = (l & 7) * 8; \
            cpa16s(sb + AKOFF + (buf) * 9216 + (uint32_t)(r * 72 + c) * 2, \
                   Kp + (size_t)(k0 + r) * HD_ + c); \
            cpa16s(sb + AVOFF + (buf) * 9216 + (uint32_t)(r * 72 + c) * 2, \
                   Vp + (size_t)(k0 + r) * HD_ + c); \
        } \
        if (tid < 16) cpa16s(sb + AMOFF + (buf) * 256 + tid * 16, amp + k0 + tid * 4); \
    } while (0)

    LOADH(0, 0);
    cp_commit();

    uint32_t qf[2][4][4];
    float oacc[2][8][4];
#pragma unroll
    for (int mi = 0; mi < 2; mi++)
#pragma unroll
        for (int i = 0; i < 8; i++)
#pragma unroll
            for (int j = 0; j < 4; j++) oacc[mi][i][j] = 0.f;
    float lsum[2][2] = {{0.f, 0.f}, {0.f, 0.f}};

    for (int ih = 0; ih < nh; ih++) {
        cp_wait0();
        __syncthreads();
        if (ih + 1 < nh) LOADH(ih + 1, (ih + 1) & 1);
        cp_commit();

        if (ih == 0) {
#pragma unroll
            for (int mi = 0; mi < 2; mi++)
#pragma unroll
                for (int kk = 0; kk < 4; kk++) {
                    int row = wid * 32 + mi * 16 + (lane & 7) + ((lane >> 3) & 1) * 8;
                    int col = kk * 16 + (lane >> 4) * 8;
                    ldmx4(qf[mi][kk], sb + AQOFF + (uint32_t)(row * 72 + col) * 2);
                }
        }

        const int buf = ih & 1;
        const uint32_t ksb = sb + AKOFF + buf * 9216;
        const uint32_t vsb = sb + AVOFF + buf * 9216;
        const float* mskf = (const float*)(smraw + AMOFF + buf * 256);

        float sacc[2][8][4];
#pragma unroll
        for (int mi = 0; mi < 2; mi++)
#pragma unroll
            for (int i = 0; i < 8; i++)
#pragma unroll
                for (int j = 0; j < 4; j++) sacc[mi][i][j] = 0.f;

#pragma unroll
        for (int kk = 0; kk < 4; kk++) {
#pragma unroll
            for (int jp = 0; jp < 4; jp++) {
                int row = jp * 16 + (lane & 7) + ((lane >> 3) & 1) * 8;
                int col = kk * 16 + (lane >> 4) * 8;
                uint32_t r4[4];
                ldmx4(r4, ksb + (uint32_t)(row * 72 + col) * 2);
#pragma unroll
                for (int mi = 0; mi < 2; mi++) {
                    mma16816(sacc[mi][jp * 2],     qf[mi][kk], r4[0], r4[2]);
                    mma16816(sacc[mi][jp * 2 + 1], qf[mi][kk], r4[1], r4[3]);
                }
            }
        }

        uint32_t pf[2][4][4];
#pragma unroll
        for (int mi = 0; mi < 2; mi++) {
#pragma unroll
            for (int j = 0; j < 8; j++) {
                const int n0 = j * 8 + 2 * (lane & 3);
                const float mk0 = mskf[n0];
                const float mk1 = mskf[n0 + 1];
                float e0 = exp2f(fmaf(sacc[mi][j][0], SCL2_, mk0));
                float e1 = exp2f(fmaf(sacc[mi][j][1], SCL2_, mk1));
                float e2 = exp2f(fmaf(sacc[mi][j][2], SCL2_, mk0));
                float e3 = exp2f(fmaf(sacc[mi][j][3], SCL2_, mk1));
                lsum[mi][0] += e0 + e1;
                lsum[mi][1] += e2 + e3;
                const int kk2 = j >> 1;
                if ((j & 1) == 0) {
                    pf[mi][kk2][0] = packbf2(e0, e1);
                    pf[mi][kk2][1] = packbf2(e2, e3);
                } else {
                    pf[mi][kk2][2] = packbf2(e0, e1);
                    pf[mi][kk2][3] = packbf2(e2, e3);
                }
            }
        }

#pragma unroll
        for (int kk2 = 0; kk2 < 4; kk2++) {
#pragma unroll
            for (int jp = 0; jp < 4; jp++) {
                int row = kk2 * 16 + (lane & 7) + ((lane >> 3) & 1) * 8;
                int col = jp * 16 + (lane >> 4) * 8;
                uint32_t r4[4];
                ldmx4t(r4, vsb + (uint32_t)(row * 72 + col) * 2);
#pragma unroll
                for (int mi = 0; mi < 2; mi++) {
                    mma16816(oacc[mi][jp * 2],     pf[mi][kk2], r4[0], r4[1]);
                    mma16816(oacc[mi][jp * 2 + 1], pf[mi][kk2], r4[2], r4[3]);
                }
            }
        }
    }
#undef LOADH

#pragma unroll
    for (int mi = 0; mi < 2; mi++) {
        lsum[mi][0] += __shfl_xor_sync(0xffffffffu, lsum[mi][0], 1);
        lsum[mi][0] += __shfl_xor_sync(0xffffffffu, lsum[mi][0], 2);
        lsum[mi][1] += __shfl_xor_sync(0xffffffffu, lsum[mi][1], 1);
        lsum[mi][1] += __shfl_xor_sync(0xffffffffu, lsum[mi][1], 2);
        const float inv0 = 1.0f / lsum[mi][0];
        const float inv1 = 1.0f / lsum[mi][1];
        const int row0 = q0 + wid * 32 + mi * 16 + (lane >> 2);
#pragma unroll
        for (int j2 = 0; j2 < 8; j2++) {
            const int col = h * HD_ + j2 * 8 + 2 * (lane & 3);
            size_t off0 = (size_t)(b * S_ + row0) * D_ + col;
            size_t off1 = (size_t)(b * S_ + row0 + 8) * D_ + col;
            *(__nv_bfloat162*)(ctx + off0) =
                __floats2bfloat162_rn(oacc[mi][j2][0] * inv0, oacc[mi][j2][1] * inv0);
            *(__nv_bfloat162*)(ctx + off1) =
                __floats2bfloat162_rn(oacc[mi][j2][2] * inv1, oacc[mi][j2][3] * inv1);
        }
    }
}

// ---------------------------------------------------------------------------
// Row LayerNorm over [M, 1024]: warp-per-row, barrier-free.
// CTA of 256 = 8 warps = 8 rows; each lane holds 8 float4 (full row/warp).
// ---------------------------------------------------------------------------
__global__ __launch_bounds__(256) void ln_kernel(
    const float* __restrict__ Y, const float* __restrict__ gamma,
    const float* __restrict__ beta, float* __restrict__ O)
{
    const int wid = threadIdx.x >> 5, lane = threadIdx.x & 31;
    const int row = blockIdx.x * 8 + wid;
    const float* yr = Y + (size_t)row * D_;
    float4 v[8];
    float s = 0.f, sq = 0.f;
#pragma unroll
    for (int i = 0; i < 8; i++) {
        v[i] = *(const float4*)(yr + i * 128 + lane * 4);
        s  += v[i].x + v[i].y + v[i].z + v[i].w;
        sq += v[i].x * v[i].x + v[i].y * v[i].y
            + v[i].z * v[i].z + v[i].w * v[i].w;
    }
#pragma unroll
    for (int o = 16; o; o >>= 1) {
        s  += __shfl_xor_sync(0xffffffffu, s, o);
        sq += __shfl_xor_sync(0xffffffffu, sq, o);
    }
    const float mu   = s * (1.0f / D_);
    const float var  = sq * (1.0f / D_) - mu * mu;
    const float rstd = rsqrtf(var + 1e-6f);
    float* orow = O + (size_t)row * D_;
#pragma unroll
    for (int i = 0; i < 8; i++) {
        const float4 g  = *(const float4*)(gamma + i * 128 + lane * 4);
        const float4 be = *(const float4*)(beta  + i * 128 + lane * 4);
        float4 o;
        o.x = (v[i].x - mu) * rstd * g.x + be.x;
        o.y = (v[i].y - mu) * rstd * g.y + be.y;
        o.z = (v[i].z - mu) * rstd * g.z + be.z;
        o.w = (v[i].w - mu) * rstd * g.w + be.w;
        *(float4*)(orow + i * 128 + lane * 4) = o;
    }
}

// ---------------------------------------------------------------------------
// Launch
// ---------------------------------------------------------------------------
extern "C" void kernel_launch(void* const* d_in, const int* in_sizes, int n_in,
                              void* d_out, int out_size)
{
    const float* x     = (const float*)d_in[0];
    const int*   mask  = (const int*)d_in[1];
    const float* wq    = (const float*)d_in[2];
    const float* bq    = (const float*)d_in[3];
    const float* wk    = (const float*)d_in[4];
    const float* bk    = (const float*)d_in[5];
    const float* wv    = (const float*)d_in[6];
    const float* bv    = (const float*)d_in[7];
    const float* wo    = (const float*)d_in[8];
    const float* bo    = (const float*)d_in[9];
    const float* gamma = (const float*)d_in[10];
    const float* beta  = (const float*)d_in[11];
    float* out = (float*)d_out;

    __nv_bfloat16 *xb, *wqb, *wkb, *wvb, *wob, *Qb, *Kb, *Vb, *ctxb;
    float *yp, *amaskp;
    int *kidxp, *kcntp;
    cudaGetSymbolAddress((void**)&xb,  g_xb);
    cudaGetSymbolAddress((void**)&wqb, g_wqb);
    cudaGetSymbolAddress((void**)&wkb, g_wkb);
    cudaGetSymbolAddress((void**)&wvb, g_wvb);
    cudaGetSymbolAddress((void**)&wob, g_wob);
    cudaGetSymbolAddress((void**)&Qb,  g_Qb);
    cudaGetSymbolAddress((void**)&Kb,  g_Kb);
    cudaGetSymbolAddress((void**)&Vb,  g_Vb);
    cudaGetSymbolAddress((void**)&ctxb, g_ctxb);
    cudaGetSymbolAddress((void**)&yp,  g_y);
    cudaGetSymbolAddress((void**)&kidxp,  g_kidx);
    cudaGetSymbolAddress((void**)&amaskp, g_amask);
    cudaGetSymbolAddress((void**)&kcntp,  g_kcnt);

    cudaFuncSetAttribute(gemm_mma_kernel,
                         cudaFuncAttributeMaxDynamicSharedMemorySize, GEMM_SMEM);
    cudaFuncSetAttribute(attn_kernel,
                         cudaFuncAttributeMaxDynamicSharedMemorySize, ATTN_SMEM);

    prologue_kernel<<<CVTB + B_, 256>>>(
        x, wq, wk, wv, wo, xb, wqb, wkb, wvb, wob,
        mask, kidxp, amaskp, kcntp);

    dim3 gQKV(D_ / 128, M_ / 128, 3);   // (8, 64, 3); K/V CTAs self-prune
    gemm_mma_kernel<<<gQKV, 256, GEMM_SMEM>>>(
        xb, wqb, wkb, wvb, bq, bk, bv, nullptr, Qb, Kb, Vb, nullptr, 1,
        kidxp, kcntp);

    dim3 gAttn(S_ / 128, B_ * H_);      // (8, 128)
    attn_kernel<<<gAttn, 128, ATTN_SMEM>>>(Qb, Kb, Vb, amaskp, kcntp, ctxb);

    dim3 gO(D_ / 128, M_ / 128, 1);
    gemm_mma_kernel<<<gO, 256, GEMM_SMEM>>>(
        ctxb, wob, wob, wob, bo, bo, bo, x, nullptr, nullptr, nullptr, yp, 0,
        kidxp, kcntp);

    ln_kernel<<<M_ / 8, 256>>>(yp, gamma, beta, out);
}

// round 17
// speedup vs baseline: 1.0173x; 1.0001x over previous
#include <cuda_runtime.h>
#include <cuda_bf16.h>
#include <math.h>
#include <cstdint>

#define B_  8
#define S_  1024
#define H_  16
#define HD_ 64
#define D_  1024
#define M_  (B_ * S_)       // 8192
// pad additive mask, pre-scaled by log2(e) for the exp2 path
#define PADV_ (-14426.950408889634f)
#define SCL2_ (0.18033688011112042f)   // 0.125 * log2(e)

// ---------------- scratch (no allocs allowed) ----------------
__device__ __nv_bfloat16 g_xb[M_ * D_];
__device__ __nv_bfloat16 g_wqb[D_ * D_];   // native [K][N] layout, bf16
__device__ __nv_bfloat16 g_wkb[D_ * D_];
__device__ __nv_bfloat16 g_wvb[D_ * D_];
__device__ __nv_bfloat16 g_wob[D_ * D_];
__device__ __nv_bfloat16 g_Qb[M_ * D_];    // [B*H][S][HD]
__device__ __nv_bfloat16 g_Kb[M_ * D_];    // compacted keys per (b,h)
__device__ __nv_bfloat16 g_Vb[M_ * D_];    // compacted values per (b,h)
__device__ __nv_bfloat16 g_ctxb[M_ * D_];  // [B*S][D]
__device__ float g_y[M_ * D_];
__device__ int   g_kidx[B_ * S_];          // compacted unmasked key indices
__device__ float g_amask[B_ * S_];         // 0 real key / PADV_ pad (pre-scaled)
__device__ int   g_kcnt[B_];               // unmasked count per batch

// ---------------- helpers ----------------
__device__ __forceinline__ uint32_t smem_u32(const void* p) {
    uint32_t a;
    asm("{ .reg .u64 t; cvta.to.shared.u64 t, %1; cvt.u32.u64 %0, t; }"
        : "=r"(a) : "l"(p));
    return a;
}
__device__ __forceinline__ void cpa16s(uint32_t s, const void* g) {
    asm volatile("cp.async.cg.shared.global [%0], [%1], 16;\n" :: "r"(s), "l"(g));
}
__device__ __forceinline__ void cp_commit() { asm volatile("cp.async.commit_group;\n"); }
__device__ __forceinline__ void cp_wait0()  { asm volatile("cp.async.wait_group 0;\n" ::: "memory"); }
__device__ __forceinline__ void cp_wait1()  { asm volatile("cp.async.wait_group 1;\n" ::: "memory"); }

__device__ __forceinline__ void ldmx4(uint32_t* r, uint32_t addr) {
    asm volatile("ldmatrix.sync.aligned.m8n8.x4.shared.b16 {%0,%1,%2,%3}, [%4];"
        : "=r"(r[0]), "=r"(r[1]), "=r"(r[2]), "=r"(r[3]) : "r"(addr));
}
__device__ __forceinline__ void ldmx4t(uint32_t* r, uint32_t addr) {
    asm volatile("ldmatrix.sync.aligned.m8n8.x4.trans.shared.b16 {%0,%1,%2,%3}, [%4];"
        : "=r"(r[0]), "=r"(r[1]), "=r"(r[2]), "=r"(r[3]) : "r"(addr));
}
__device__ __forceinline__ void mma16816(float* c, const uint32_t* a,
                                         uint32_t b0, uint32_t b1) {
    asm volatile("mma.sync.aligned.m16n8k16.row.col.f32.bf16.bf16.f32 "
        "{%0,%1,%2,%3}, {%4,%5,%6,%7}, {%8,%9}, {%0,%1,%2,%3};"
        : "+f"(c[0]), "+f"(c[1]), "+f"(c[2]), "+f"(c[3])
        : "r"(a[0]), "r"(a[1]), "r"(a[2]), "r"(a[3]), "r"(b0), "r"(b1));
}
__device__ __forceinline__ uint32_t packbf2(float lo, float hi) {
    __nv_bfloat162 t = __floats2bfloat162_rn(lo, hi);
    return *(uint32_t*)&t;
}

// ---------------------------------------------------------------------------
// Fused prologue: fp32->bf16 conversion of x + 4 weights (blocks 0..CVTB-1)
// and per-batch mask scan/compaction (blocks CVTB..CVTB+7).
// ---------------------------------------------------------------------------
#define XN (M_ * D_)          // 8388608
#define WN (D_ * D_)          // 1048576
#define CVTB ((XN + 4 * WN) / 1024)   // 12288

__global__ __launch_bounds__(256) void prologue_kernel(
    const float* __restrict__ x,
    const float* __restrict__ wq, const float* __restrict__ wk,
    const float* __restrict__ wv, const float* __restrict__ wo,
    __nv_bfloat16* __restrict__ xb,
    __nv_bfloat16* __restrict__ wqb, __nv_bfloat16* __restrict__ wkb,
    __nv_bfloat16* __restrict__ wvb, __nv_bfloat16* __restrict__ wob,
    const int* __restrict__ mask, int* __restrict__ kidx,
    float* __restrict__ amask, int* __restrict__ kcnt)
{
    if (blockIdx.x >= CVTB) {
        // ---- mask scan for batch b ----
        __shared__ int m[1024];
        __shared__ int wsum[8];
        __shared__ int totsh;
        const int b = blockIdx.x - CVTB, t = threadIdx.x;
        const int lane = t & 31, w = t >> 5;
#pragma unroll
        for (int i = 0; i < 4; i++) m[t * 4 + i] = mask[b * 1024 + t * 4 + i];
        __syncthreads();
        int f[4], c = 0;
#pragma unroll
        for (int i = 0; i < 4; i++) { f[i] = (m[t * 4 + i] == 0); c += f[i]; }
        int ex = c;
#pragma unroll
        for (int o = 1; o < 32; o <<= 1) {
            int v = __shfl_up_sync(0xffffffffu, ex, o);
            if (lane >= o) ex += v;
        }
        int wtot = __shfl_sync(0xffffffffu, ex, 31);
        ex -= c;
        if (lane == 31) wsum[w] = wtot;
        __syncthreads();
        if (t == 0) {
            int run = 0;
#pragma unroll
            for (int i = 0; i < 8; i++) { int v = wsum[i]; wsum[i] = run; run += v; }
            totsh = run;
            kcnt[b] = run;
        }
        __syncthreads();
        int base = wsum[w] + ex;
        const int total = totsh;
#pragma unroll
        for (int i = 0; i < 4; i++) {
            if (f[i]) kidx[b * 1024 + base++] = t * 4 + i;
        }
#pragma unroll
        for (int i = 0; i < 4; i++) {
            int j = t * 4 + i;
            amask[b * 1024 + j] = (j < total) ? 0.0f : PADV_;
            if (j >= total) kidx[b * 1024 + j] = 0;
        }
        return;
    }

    // ---- fp32 -> bf16 conversion ----
    long long i = (long long)(blockIdx.x * 256 + threadIdx.x) * 4;
    const float* src;
    __nv_bfloat16* dst;
    long long off;
    if (i < XN)                { src = x;  dst = xb;  off = i; }
    else if (i < XN + WN)      { src = wq; dst = wqb; off = i - XN; }
    else if (i < XN + 2 * WN)  { src = wk; dst = wkb; off = i - XN - WN; }
    else if (i < XN + 3 * WN)  { src = wv; dst = wvb; off = i - XN - 2 * WN; }
    else                       { src = wo; dst = wob; off = i - XN - 3 * WN; }
    float4 v = *(const float4*)(src + off);
    *(__nv_bfloat162*)(dst + off)     = __floats2bfloat162_rn(v.x, v.y);
    *(__nv_bfloat162*)(dst + off + 2) = __floats2bfloat162_rn(v.z, v.w);
}

// ---------------------------------------------------------------------------
// mma.sync GEMM: block 128x128, 8 warps 2(m)x4(n), warp 64x32, BK=64,
// 3-stage ring, one sync per K-step.
// gather mode (heads_mode && z!=0): A-rows gathered through kidx; pad-region
// CTAs exit immediately.
// ---------------------------------------------------------------------------
#define GAST 18432
#define GBST 17408
#define GBBASE (3 * GAST)
#define GSIDX (3 * GAST + 3 * GBST)       // row-index array (128 ints)
#define GEMM_SMEM (GSIDX + 512)

__global__ __launch_bounds__(256, 2) void gemm_mma_kernel(
    const __nv_bfloat16* __restrict__ A,
    const __nv_bfloat16* __restrict__ W0, const __nv_bfloat16* __restrict__ W1,
    const __nv_bfloat16* __restrict__ W2,
    const float* __restrict__ b0p, const float* __restrict__ b1p,
    const float* __restrict__ b2p,
    const float* __restrict__ resid,
    __nv_bfloat16* __restrict__ O0, __nv_bfloat16* __restrict__ O1,
    __nv_bfloat16* __restrict__ O2,
    float* __restrict__ OutF, int heads_mode,
    const int* __restrict__ kidx, const int* __restrict__ kcnt)
{
    extern __shared__ char smraw[];
    const uint32_t sb = smem_u32(smraw);
    const int tid = threadIdx.x;
    const int wid = tid >> 5, lane = tid & 31;
    const int wm = wid >> 2, wn = wid & 3;
    const int bm = blockIdx.y * 128, bn = blockIdx.x * 128;
    const int z = blockIdx.z;

    const int gather = heads_mode && (z != 0);
    if (gather) {
        const int cnt = kcnt[bm >> 10];
        if ((bm & 1023) >= ((cnt + 127) & ~127)) return;
    }

    const __nv_bfloat16* W = (z == 0) ? W0 : (z == 1) ? W1 : W2;
    const float* bias       = (z == 0) ? b0p : (z == 1) ? b1p : b2p;
    __nv_bfloat16* OutB     = (z == 0) ? O0 : (z == 1) ? O1 : O2;

    int* srows = (int*)(smraw + GSIDX);
    if (tid < 128) {
        int m = bm + tid;
        srows[tid] = gather ? ((m & ~1023) + kidx[m]) : m;
    }
    __syncthreads();

    const __nv_bfloat16* Wg = W + bn;

    float acc[16][4];
#pragma unroll
    for (int i = 0; i < 16; i++)
#pragma unroll
        for (int j = 0; j < 4; j++) acc[i][j] = 0.f;

#define GLOAD(u, st) do { \
        const uint32_t as = sb + (st) * GAST; \
        const uint32_t bs = sb + GBBASE + (st) * GBST; \
        const __nv_bfloat16* wp = Wg + (size_t)((u) * 64) * D_; \
        _Pragma("unroll") \
        for (int i = 0; i < 4; i++) { \
            int idx = i * 256 + tid; \
            int ra = idx >> 3, ca = (idx & 7) * 8; \
            cpa16s(as + (uint32_t)(ra * 72 + ca) * 2, \
                   A + (size_t)srows[ra] * D_ + (u) * 64 + ca); \
            int rb = idx >> 4, cb = (idx & 15) * 8; \
            cpa16s(bs + (uint32_t)(rb * 136 + cb) * 2, wp + (size_t)rb * D_ + cb); \
        } \
    } while (0)

    GLOAD(0, 0); cp_commit();
    GLOAD(1, 1); cp_commit();

    int sr = 0, sw = 2;
    for (int u = 0; u < 16; u++) {
        cp_wait1();
        __syncthreads();
        if (u + 2 < 16) GLOAD(u + 2, sw);
        cp_commit();

        const uint32_t as = sb + sr * GAST;
        const uint32_t bs = sb + GBBASE + sr * GBST;
#pragma unroll
        for (int kk = 0; kk < 4; kk++) {
            uint32_t a[4][4];
#pragma unroll
            for (int i = 0; i < 4; i++) {
                int row = wm * 64 + i * 16 + (lane & 7) + ((lane >> 3) & 1) * 8;
                int col = kk * 16 + (lane >> 4) * 8;
                ldmx4(a[i], as + (uint32_t)(row * 72 + col) * 2);
            }
#pragma unroll
            for (int jp = 0; jp < 2; jp++) {
                int row = kk * 16 + (lane & 7) + ((lane >> 3) & 1) * 8;
                int col = wn * 32 + jp * 16 + (lane >> 4) * 8;
                uint32_t r4[4];
                ldmx4t(r4, bs + (uint32_t)(row * 136 + col) * 2);
#pragma unroll
                for (int i = 0; i < 4; i++) {
                    mma16816(acc[i * 4 + jp * 2],     a[i], r4[0], r4[1]);
                    mma16816(acc[i * 4 + jp * 2 + 1], a[i], r4[2], r4[3]);
                }
            }
        }
        sr = (sr == 2) ? 0 : sr + 1;
        sw = (sw == 2) ? 0 : sw + 1;
    }
#undef GLOAD

#pragma unroll
    for (int i = 0; i < 4; i++) {
        const int m0 = bm + wm * 64 + i * 16 + (lane >> 2);
#pragma unroll
        for (int j = 0; j < 4; j++) {
            const int n = bn + wn * 32 + j * 8 + 2 * (lane & 3);
            const float2 bb = *(const float2*)(bias + n);
            float v0 = acc[i * 4 + j][0] + bb.x;
            float v1 = acc[i * 4 + j][1] + bb.y;
            float v2 = acc[i * 4 + j][2] + bb.x;
            float v3 = acc[i * 4 + j][3] + bb.y;
            if (heads_mode) {
                const int h = n >> 6, hd = n & 63;
                {
                    int b = m0 >> 10, s = m0 & 1023;
                    *(__nv_bfloat162*)(OutB + (((size_t)((b << 4) + h)) << 16)
                                       + ((size_t)s << 6) + hd)
                        = __floats2bfloat162_rn(v0, v1);
                }
                {
                    int m1 = m0 + 8;
                    int b = m1 >> 10, s = m1 & 1023;
                    *(__nv_bfloat162*)(OutB + (((size_t)((b << 4) + h)) << 16)
                                       + ((size_t)s << 6) + hd)
                        = __floats2bfloat162_rn(v2, v3);
                }
            } else {
                size_t off0 = (size_t)m0 * D_ + n;
                size_t off1 = (size_t)(m0 + 8) * D_ + n;
                float2 r0 = *(const float2*)(resid + off0);
                float2 r1 = *(const float2*)(resid + off1);
                *(float2*)(OutF + off0) = make_float2(v0 + r0.x, v1 + r0.y);
                *(float2*)(OutF + off1) = make_float2(v2 + r1.x, v3 + r1.y);
            }
        }
    }
}

// ---------------------------------------------------------------------------
// Attention over PRE-COMPACTED K/V: direct sequential loads, 4 warps x 32
// q-rows, 64-key half-tiles. exp via exp2 with pre-merged constants.
// ---------------------------------------------------------------------------
#define AQOFF 0
#define AKOFF 18432
#define AVOFF (18432 + 18432)
#define AMOFF (18432 + 36864)
#define ATTN_SMEM (18432 + 36864 + 512 + 128)

__global__ __launch_bounds__(128, 2) void attn_kernel(
    const __nv_bfloat16* __restrict__ Q, const __nv_bfloat16* __restrict__ K,
    const __nv_bfloat16* __restrict__ V,
    const float* __restrict__ amask, const int* __restrict__ kcnt,
    __nv_bfloat16* __restrict__ ctx)
{
    extern __shared__ char smraw[];
    const uint32_t sb = smem_u32(smraw);
    const int tid = threadIdx.x;
    const int wid = tid >> 5, lane = tid & 31;
    const int bh = blockIdx.y;
    const int b = bh >> 4, h = bh & 15;
    const int q0 = blockIdx.x * 128;

    const __nv_bfloat16* Qp = Q + (((size_t)bh) << 16) + (size_t)q0 * HD_;
    const __nv_bfloat16* Kp = K + (((size_t)bh) << 16);
    const __nv_bfloat16* Vp = V + (((size_t)bh) << 16);
    const float* amp = amask + b * 1024;
    const int nh = (kcnt[b] + 63) >> 6;

#pragma unroll
    for (int i = 0; i < 8; i++) {
        int l = i * 128 + tid;
        int r = l >> 3, c = (l & 7) * 8;
        cpa16s(sb + AQOFF + (uint32_t)(r * 72 + c) * 2, Qp + (size_t)r * HD_ + c);
    }
#define LOADH(ih, buf) do { \
        const int k0 = (ih) * 64; \
        _Pragma("unroll") \
        for (int ii = 0; ii < 4; ii++) { \
            int l = ii * 128 + tid; int r = l >> 3, c = (l & 7) * 8; \
            cpa16s(sb + AKOFF + (buf) * 9216 + (uint32_t)(r * 72 + c) * 2, \
                   Kp + (size_t)(k0 + r) * HD_ + c); \
            cpa16s(sb + AVOFF + (buf) * 9216 + (uint32_t)(r * 72 + c) * 2, \
                   Vp + (size_t)(k0 + r) * HD_ + c); \
        } \
        if (tid < 16) cpa16s(sb + AMOFF + (buf) * 256 + tid * 16, amp + k0 + tid * 4); \
    } while (0)

    LOADH(0, 0);
    cp_commit();

    uint32_t qf[2][4][4];
    float oacc[2][8][4];
#pragma unroll
    for (int mi = 0; mi < 2; mi++)
#pragma unroll
        for (int i = 0; i < 8; i++)
#pragma unroll
            for (int j = 0; j < 4; j++) oacc[mi][i][j] = 0.f;
    float lsum[2][2] = {{0.f, 0.f}, {0.f, 0.f}};

    for (int ih = 0; ih < nh; ih++) {
        cp_wait0();
        __syncthreads();
        if (ih + 1 < nh) LOADH(ih + 1, (ih + 1) & 1);
        cp_commit();

        if (ih == 0) {
#pragma unroll
            for (int mi = 0; mi < 2; mi++)
#pragma unroll
                for (int kk = 0; kk < 4; kk++) {
                    int row = wid * 32 + mi * 16 + (lane & 7) + ((lane >> 3) & 1) * 8;
                    int col = kk * 16 + (lane >> 4) * 8;
                    ldmx4(qf[mi][kk], sb + AQOFF + (uint32_t)(row * 72 + col) * 2);
                }
        }

        const int buf = ih & 1;
        const uint32_t ksb = sb + AKOFF + buf * 9216;
        const uint32_t vsb = sb + AVOFF + buf * 9216;
        const float* mskf = (const float*)(smraw + AMOFF + buf * 256);

        float sacc[2][8][4];
#pragma unroll
        for (int mi = 0; mi < 2; mi++)
#pragma unroll
            for (int i = 0; i < 8; i++)
#pragma unroll
                for (int j = 0; j < 4; j++) sacc[mi][i][j] = 0.f;

#pragma unroll
        for (int kk = 0; kk < 4; kk++) {
#pragma unroll
            for (int jp = 0; jp < 4; jp++) {
                int row = jp * 16 + (lane & 7) + ((lane >> 3) & 1) * 8;
                int col = kk * 16 + (lane >> 4) * 8;
                uint32_t r4[4];
                ldmx4(r4, ksb + (uint32_t)(row * 72 + col) * 2);
#pragma unroll
                for (int mi = 0; mi < 2; mi++) {
                    mma16816(sacc[mi][jp * 2],     qf[mi][kk], r4[0], r4[2]);
                    mma16816(sacc[mi][jp * 2 + 1], qf[mi][kk], r4[1], r4[3]);
                }
            }
        }

        uint32_t pf[2][4][4];
#pragma unroll
        for (int mi = 0; mi < 2; mi++) {
#pragma unroll
            for (int j = 0; j < 8; j++) {
                const int n0 = j * 8 + 2 * (lane & 3);
                const float mk0 = mskf[n0];
                const float mk1 = mskf[n0 + 1];
                float e0 = exp2f(fmaf(sacc[mi][j][0], SCL2_, mk0));
                float e1 = exp2f(fmaf(sacc[mi][j][1], SCL2_, mk1));
                float e2 = exp2f(fmaf(sacc[mi][j][2], SCL2_, mk0));
                float e3 = exp2f(fmaf(sacc[mi][j][3], SCL2_, mk1));
                lsum[mi][0] += e0 + e1;
                lsum[mi][1] += e2 + e3;
                const int kk2 = j >> 1;
                if ((j & 1) == 0) {
                    pf[mi][kk2][0] = packbf2(e0, e1);
                    pf[mi][kk2][1] = packbf2(e2, e3);
                } else {
                    pf[mi][kk2][2] = packbf2(e0, e1);
                    pf[mi][kk2][3] = packbf2(e2, e3);
                }
            }
        }

#pragma unroll
        for (int kk2 = 0; kk2 < 4; kk2++) {
#pragma unroll
            for (int jp = 0; jp < 4; jp++) {
                int row = kk2 * 16 + (lane & 7) + ((lane >> 3) & 1) * 8;
                int col = jp * 16 + (lane >> 4) * 8;
                uint32_t r4[4];
                ldmx4t(r4, vsb + (uint32_t)(row * 72 + col) * 2);
#pragma unroll
                for (int mi = 0; mi < 2; mi++) {
                    mma16816(oacc[mi][jp * 2],     pf[mi][kk2], r4[0], r4[1]);
                    mma16816(oacc[mi][jp * 2 + 1], pf[mi][kk2], r4[2], r4[3]);
                }
            }
        }
    }
#undef LOADH

#pragma unroll
    for (int mi = 0; mi < 2; mi++) {
        lsum[mi][0] += __shfl_xor_sync(0xffffffffu, lsum[mi][0], 1);
        lsum[mi][0] += __shfl_xor_sync(0xffffffffu, lsum[mi][0], 2);
        lsum[mi][1] += __shfl_xor_sync(0xffffffffu, lsum[mi][1], 1);
        lsum[mi][1] += __shfl_xor_sync(0xffffffffu, lsum[mi][1], 2);
        const float inv0 = 1.0f / lsum[mi][0];
        const float inv1 = 1.0f / lsum[mi][1];
        const int row0 = q0 + wid * 32 + mi * 16 + (lane >> 2);
#pragma unroll
        for (int j2 = 0; j2 < 8; j2++) {
            const int col = h * HD_ + j2 * 8 + 2 * (lane & 3);
            size_t off0 = (size_t)(b * S_ + row0) * D_ + col;
            size_t off1 = (size_t)(b * S_ + row0 + 8) * D_ + col;
            *(__nv_bfloat162*)(ctx + off0) =
                __floats2bfloat162_rn(oacc[mi][j2][0] * inv0, oacc[mi][j2][1] * inv0);
            *(__nv_bfloat162*)(ctx + off1) =
                __floats2bfloat162_rn(oacc[mi][j2][2] * inv1, oacc[mi][j2][3] * inv1);
        }
    }
}

// ---------------------------------------------------------------------------
// Row LayerNorm over [M, 1024]: warp-per-row, barrier-free.
// CTA of 256 = 8 warps = 8 rows; each lane holds 8 float4 (full row/warp).
// ---------------------------------------------------------------------------
__global__ __launch_bounds__(256) void ln_kernel(
    const float* __restrict__ Y, const float* __restrict__ gamma,
    const float* __restrict__ beta, float* __restrict__ O)
{
    const int wid = threadIdx.x >> 5, lane = threadIdx.x & 31;
    const int row = blockIdx.x * 8 + wid;
    const float* yr = Y + (size_t)row * D_;
    float4 v[8];
    float s = 0.f, sq = 0.f;
#pragma unroll
    for (int i = 0; i < 8; i++) {
        v[i] = *(const float4*)(yr + i * 128 + lane * 4);
        s  += v[i].x + v[i].y + v[i].z + v[i].w;
        sq += v[i].x * v[i].x + v[i].y * v[i].y
            + v[i].z * v[i].z + v[i].w * v[i].w;
    }
#pragma unroll
    for (int o = 16; o; o >>= 1) {
        s  += __shfl_xor_sync(0xffffffffu, s, o);
        sq += __shfl_xor_sync(0xffffffffu, sq, o);
    }
    const float mu   = s * (1.0f / D_);
    const float var  = sq * (1.0f / D_) - mu * mu;
    const float rstd = rsqrtf(var + 1e-6f);
    float* orow = O + (size_t)row * D_;
#pragma unroll
    for (int i = 0; i < 8; i++) {
        const float4 g  = *(const float4*)(gamma + i * 128 + lane * 4);
        const float4 be = *(const float4*)(beta  + i * 128 + lane * 4);
        float4 o;
        o.x = (v[i].x - mu) * rstd * g.x + be.x;
        o.y = (v[i].y - mu) * rstd * g.y + be.y;
        o.z = (v[i].z - mu) * rstd * g.z + be.z;
        o.w = (v[i].w - mu) * rstd * g.w + be.w;
        *(float4*)(orow + i * 128 + lane * 4) = o;
    }
}

// ---------------------------------------------------------------------------
// Launch
// ---------------------------------------------------------------------------
extern "C" void kernel_launch(void* const* d_in, const int* in_sizes, int n_in,
                              void* d_out, int out_size)
{
    const float* x     = (const float*)d_in[0];
    const int*   mask  = (const int*)d_in[1];
    const float* wq    = (const float*)d_in[2];
    const float* bq    = (const float*)d_in[3];
    const float* wk    = (const float*)d_in[4];
    const float* bk    = (const float*)d_in[5];
    const float* wv    = (const float*)d_in[6];
    const float* bv    = (const float*)d_in[7];
    const float* wo    = (const float*)d_in[8];
    const float* bo    = (const float*)d_in[9];
    const float* gamma = (const float*)d_in[10];
    const float* beta  = (const float*)d_in[11];
    float* out = (float*)d_out;

    __nv_bfloat16 *xb, *wqb, *wkb, *wvb, *wob, *Qb, *Kb, *Vb, *ctxb;
    float *yp, *amaskp;
    int *kidxp, *kcntp;
    cudaGetSymbolAddress((void**)&xb,  g_xb);
    cudaGetSymbolAddress((void**)&wqb, g_wqb);
    cudaGetSymbolAddress((void**)&wkb, g_wkb);
    cudaGetSymbolAddress((void**)&wvb, g_wvb);
    cudaGetSymbolAddress((void**)&wob, g_wob);
    cudaGetSymbolAddress((void**)&Qb,  g_Qb);
    cudaGetSymbolAddress((void**)&Kb,  g_Kb);
    cudaGetSymbolAddress((void**)&Vb,  g_Vb);
    cudaGetSymbolAddress((void**)&ctxb, g_ctxb);
    cudaGetSymbolAddress((void**)&yp,  g_y);
    cudaGetSymbolAddress((void**)&kidxp,  g_kidx);
    cudaGetSymbolAddress((void**)&amaskp, g_amask);
    cudaGetSymbolAddress((void**)&kcntp,  g_kcnt);

    cudaFuncSetAttribute(gemm_mma_kernel,
                         cudaFuncAttributeMaxDynamicSharedMemorySize, GEMM_SMEM);
    cudaFuncSetAttribute(attn_kernel,
                         cudaFuncAttributeMaxDynamicSharedMemorySize, ATTN_SMEM);

    prologue_kernel<<<CVTB + B_, 256>>>(
        x, wq, wk, wv, wo, xb, wqb, wkb, wvb, wob,
        mask, kidxp, amaskp, kcntp);

    dim3 gQKV(D_ / 128, M_ / 128, 3);   // (8, 64, 3); K/V CTAs self-prune
    gemm_mma_kernel<<<gQKV, 256, GEMM_SMEM>>>(
        xb, wqb, wkb, wvb, bq, bk, bv, nullptr, Qb, Kb, Vb, nullptr, 1,
        kidxp, kcntp);

    dim3 gAttn(S_ / 128, B_ * H_);      // (8, 128)
    attn_kernel<<<gAttn, 128, ATTN_SMEM>>>(Qb, Kb, Vb, amaskp, kcntp, ctxb);

    dim3 gO(D_ / 128, M_ / 128, 1);
    gemm_mma_kernel<<<gO, 256, GEMM_SMEM>>>(
        ctxb, wob, wob, wob, bo, bo, bo, x, nullptr, nullptr, nullptr, yp, 0,
        kidxp, kcntp);

    ln_kernel<<<M_ / 8, 256>>>(yp, gamma, beta, out);
}